// round 14
// baseline (speedup 1.0000x reference)
#include <cuda_runtime.h>
#include <cuda_fp16.h>

#define NS     8
#define HH     128
#define WW     128
#define HWP    (HH*WW)      // 16384
#define BB     32
#define SLICES 16           // CTAs per batch
#define SROWS  (HH/SLICES)  // 8 rows per CTA
#define EPSV   1e-8f
#define TH     4            // rows per inner tile

// ---------------- scratch (static device memory, no allocation) ----------------
// H0 plane-major [b][i*8+j][h][w]  -> warp-coalesced LDG.32 per channel
__device__ __half   g_H0[(size_t)BB*NS*NS*HWP];   // 67 MB
__device__ __half   g_r [(size_t)BB*NS*HWP];      // 8.4 MB  [b][i][h][w]
__device__ __half   g_c [(size_t)BB*NS*HWP];      // 8.4 MB  [b][j][h][w]
__device__ __half   g_mA[(size_t)BB*NS*HWP];      // 8.4 MB marginal ping
__device__ __half   g_mB[(size_t)BB*NS*HWP];      // 8.4 MB marginal pong
__device__ unsigned g_bar[BB*32] = {};            // per-batch barrier, 128B padded

// ---------------- separable gaussian weights (bandwidth 0.5, normalized) -------
constexpr double d_e2 = 0.13533528323661270231;
constexpr double d_e8 = 0.00033546262790251185;
constexpr double d_s  = 1.0 + 2.0*d_e2 + 2.0*d_e8;
#define KW0 ((float)(d_e8/d_s))
#define KW1 ((float)(d_e2/d_s))
#define KW2 ((float)(1.0 /d_s))

// ---------------- per-batch software barrier (monotonic counter) ----------------
__device__ __forceinline__ void batch_barrier(int b, unsigned target, int tid) {
    __syncthreads();
    if (tid == 0) {
        __threadfence();
        atomicAdd(&g_bar[b*32], 1u);
        while (atomicAdd(&g_bar[b*32], 0u) < target) { }
        __threadfence();
    }
    __syncthreads();
}

// ---------------- one TH-row tile of a half step --------------------------------
// MODE 0: smooth marg_in -> r /= (s+eps); marg_out_j = c_j * sum_i H0[i][j]*r_i
// MODE 1: smooth marg_in -> c /= (s+eps); marg_out_i = r_i * sum_j H0[i][j]*c_j
template<int MODE>
__device__ __forceinline__ void half_tile(
    int b, int h0, int tid,
    const __half* __restrict__ min_, __half* __restrict__ mout,
    __half* __restrict__ upd, const __half* __restrict__ oth,
    __half (*sm_m)[NS][WW], float (*sm_t)[NS][WW])
{
    // ---- stage 1: load marginal tile (rows h0-2 .. h0+TH+1, circular), L2 path -
    #pragma unroll
    for (int k = 0; k < 4; k++) {               // 1024 uint4 / 256 threads
        int idx = tid + k*256;
        int rr  = idx >> 7;                     // 0..7
        int rem = idx & 127;
        int ch  = rem >> 4;
        int w8  = (rem & 15) << 3;
        int gh  = (h0 - 2 + rr) & (HH-1);
        uint4 v = __ldcg((const uint4*)(min_ + ((size_t)(b*NS + ch))*HWP + gh*WW + w8));
        *(uint4*)(&sm_m[rr][ch][w8]) = v;
    }
    __syncthreads();

    // ---- stage 2: vertical 5-tap, half2 granularity (2048 units / 256 thr) -----
    #pragma unroll
    for (int k = 0; k < 8; k++) {
        int e2 = tid + k*256;
        int r  = e2 >> 9;                       // 0..3
        int ch = (e2 >> 6) & 7;
        int w2 = (e2 & 63) << 1;
        float2 a0 = __half22float2(*(const __half2*)(&sm_m[r  ][ch][w2]));
        float2 a1 = __half22float2(*(const __half2*)(&sm_m[r+1][ch][w2]));
        float2 a2 = __half22float2(*(const __half2*)(&sm_m[r+2][ch][w2]));
        float2 a3 = __half22float2(*(const __half2*)(&sm_m[r+3][ch][w2]));
        float2 a4 = __half22float2(*(const __half2*)(&sm_m[r+4][ch][w2]));
        float2 o;
        o.x = KW0*a0.x + KW1*a1.x + KW2*a2.x + KW1*a3.x + KW0*a4.x;
        o.y = KW0*a0.y + KW1*a1.y + KW2*a2.y + KW1*a3.y + KW0*a4.y;
        *(float2*)(&sm_t[r][ch][w2]) = o;
    }
    __syncthreads();

    // ---- stage 3: horizontal 5-tap, factor update, contraction (2 px/thread) ---
    const int row = tid >> 6;                   // 0..3
    const int w0  = (tid & 63) << 1;            // 0,2,..,126
    const int h   = h0 + row;
    const size_t pixoff = (size_t)h*WW + w0;
    const size_t hbase  = (size_t)b*NS*NS*HWP + pixoff;

    float un[NS][2];
    #pragma unroll
    for (int u = 0; u < NS; u++) {
        float tm2 = sm_t[row][u][(w0 + 126) & 127];
        float tm1 = sm_t[row][u][(w0 + 127) & 127];
        float t0  = sm_t[row][u][w0];
        float t1  = sm_t[row][u][w0 + 1];
        float tp2 = sm_t[row][u][(w0 + 2) & 127];
        float tp3 = sm_t[row][u][(w0 + 3) & 127];
        float s0 = KW0*tm2 + KW1*tm1 + KW2*t0 + KW1*t1 + KW0*tp2;
        float s1 = KW0*tm1 + KW1*t0  + KW2*t1 + KW1*tp2 + KW0*tp3;

        size_t off = ((size_t)(b*NS + u))*HWP + pixoff;
        float2 f = __half22float2(*(const __half2*)(upd + off));
        un[u][0] = __fdividef(f.x, s0 + EPSV);
        un[u][1] = __fdividef(f.y, s1 + EPSV);
        *(__half2*)(upd + off) = __floats2half2_rn(un[u][0], un[u][1]);
    }

    #pragma unroll
    for (int vh = 0; vh < 2; vh++) {
        float acc[4][2];
        #pragma unroll
        for (int v = 0; v < 4; v++) acc[v][0] = acc[v][1] = 0.f;

        #pragma unroll
        for (int u = 0; u < NS; u++) {
            #pragma unroll
            for (int v = 0; v < 4; v++) {
                int vv = vh*4 + v;
                int cc = (MODE == 0) ? (u*NS + vv) : (vv*NS + u);
                float2 f = __half22float2(*(const __half2*)(g_H0 + hbase + (size_t)cc*HWP));
                acc[v][0] += f.x * un[u][0];
                acc[v][1] += f.y * un[u][1];
            }
        }

        #pragma unroll
        for (int v = 0; v < 4; v++) {
            int vv = vh*4 + v;
            size_t off = ((size_t)(b*NS + vv))*HWP + pixoff;
            float2 o = __half22float2(*(const __half2*)(oth + off));
            *(__half2*)(mout + off) = __floats2half2_rn(acc[v][0]*o.x, acc[v][1]*o.y);
        }
    }
}

// ================= the whole pipeline in ONE persistent kernel ==================
__global__ __launch_bounds__(256, 4) void k_all(const float* __restrict__ lg,
                                                float* __restrict__ out) {
    __shared__ __align__(16) __half sm_m[TH+4][NS][WW];  // 16 KB
    __shared__ __align__(16) float  sm_t[TH  ][NS][WW];  // 16 KB

    const int cta = blockIdx.x;
    const int b   = cta >> 4;          // batch
    const int r0  = (cta & 15) * SROWS;
    const int tid = threadIdx.x;

    // ---- init own slice: H0 = exp(lg), marg0 = sum_j, r = c = 1 ----------------
    {
        const int row = r0 + (tid >> 5);
        const int w4  = (tid & 31) << 2;
        const size_t pixb = (size_t)row*WW + w4;
        const __half2 one2 = __floats2half2_rn(1.f, 1.f);
        #pragma unroll
        for (int i = 0; i < NS; i++) {
            float a0 = 0.f, a1 = 0.f, a2 = 0.f, a3 = 0.f;
            #pragma unroll
            for (int j = 0; j < NS; j++) {
                size_t off = ((size_t)(b*NS*NS + i*NS + j))*HWP + pixb;
                float4 v = *(const float4*)(lg + off);
                float e0 = expf(v.x), e1 = expf(v.y), e2 = expf(v.z), e3 = expf(v.w);
                __half2* hp = (__half2*)(g_H0 + off);
                hp[0] = __floats2half2_rn(e0, e1);
                hp[1] = __floats2half2_rn(e2, e3);
                a0 += e0; a1 += e1; a2 += e2; a3 += e3;
            }
            size_t moff = ((size_t)(b*NS + i))*HWP + pixb;
            __half2* mp = (__half2*)(g_mA + moff);
            mp[0] = __floats2half2_rn(a0, a1);
            mp[1] = __floats2half2_rn(a2, a3);
            ((__half2*)(g_r + moff))[0] = one2;
            ((__half2*)(g_r + moff))[1] = one2;
            ((__half2*)(g_c + moff))[0] = one2;
            ((__half2*)(g_c + moff))[1] = one2;
        }
    }
    unsigned phase = 1;
    batch_barrier(b, phase*SLICES, tid);

    // ---- 20 Sinkhorn iterations, barrier per half-step -------------------------
    for (int it = 0; it < 20; it++) {
        #pragma unroll
        for (int t = 0; t < 2; t++)
            half_tile<0>(b, r0 + t*TH, tid, g_mA, g_mB, g_r, g_c, sm_m, sm_t);
        phase++; batch_barrier(b, phase*SLICES, tid);

        #pragma unroll
        for (int t = 0; t < 2; t++)
            half_tile<1>(b, r0 + t*TH, tid, g_mB, g_mA, g_c, g_r, sm_m, sm_t);
        phase++; batch_barrier(b, phase*SLICES, tid);
    }

    // ---- final own slice: out = exp(lg)*r_i*c_j + eps (fp32 path) --------------
    {
        const int row = r0 + (tid >> 5);
        const int w4  = (tid & 31) << 2;
        const size_t pixb = (size_t)row*WW + w4;

        float cf[NS][4];
        #pragma unroll
        for (int j = 0; j < NS; j++) {
            uint2 cv = *(const uint2*)(g_c + ((size_t)(b*NS + j))*HWP + pixb);
            float2 c01 = __half22float2(*(__half2*)&cv.x);
            float2 c23 = __half22float2(*(__half2*)&cv.y);
            cf[j][0] = c01.x; cf[j][1] = c01.y; cf[j][2] = c23.x; cf[j][3] = c23.y;
        }
        #pragma unroll
        for (int i = 0; i < NS; i++) {
            uint2 rw = *(const uint2*)(g_r + ((size_t)(b*NS + i))*HWP + pixb);
            float2 r01 = __half22float2(*(__half2*)&rw.x);
            float2 r23 = __half22float2(*(__half2*)&rw.y);
            #pragma unroll
            for (int j = 0; j < NS; j++) {
                size_t off = ((size_t)(b*NS*NS + i*NS + j))*HWP + pixb;
                float4 v = *(const float4*)(lg + off);
                float4 o;
                o.x = expf(v.x)*r01.x*cf[j][0] + EPSV;
                o.y = expf(v.y)*r01.y*cf[j][1] + EPSV;
                o.z = expf(v.z)*r23.x*cf[j][2] + EPSV;
                o.w = expf(v.w)*r23.y*cf[j][3] + EPSV;
                *(float4*)(out + off) = o;
            }
        }
    }
}

// ================= reset barrier counters for the next (graph) replay ===========
__global__ void k_reset() {
    if (threadIdx.x < BB) g_bar[threadIdx.x*32] = 0;
}

// ================= launch =======================================================
extern "C" void kernel_launch(void* const* d_in, const int* in_sizes, int n_in,
                              void* d_out, int out_size) {
    (void)in_sizes; (void)n_in; (void)out_size;
    const float* lg  = (const float*)d_in[0];
    float*       out = (float*)d_out;

    // 512 CTAs x 256 thr; launch_bounds(256,4) + 33 KB smem guarantee all
    // 512 CTAs are simultaneously resident (capacity 592) -> barriers safe.
    k_all<<<SLICES*BB, 256>>>(lg, out);
    k_reset<<<1, 32>>>();
}